// round 11
// baseline (speedup 1.0000x reference)
#include <cuda_runtime.h>
#include <cstdint>

// Problem constants
#define NB      4
#define NN      2048
#define PP      2096128            // NN*(NN-1)/2
#define TOTALF  (NB*PP)            // 8384512 flat pair slots per output row
#define RPB     8                  // rows per block
#define GBLK    (NB * (NN / RPB))  // 1024 blocks
#define MAXC    64                 // max j-chunks (32 pairs) per row
#define CPBLK   (RPB * MAXC)       // 512 mask slots per block
#define THREADS 256
#define FULL    0xffffffffu

// d2 <= 25.0f + 1ulp  <=>  sqrtf(d2) <= 5.0f (correctly rounded sqrt)
#define THR_BITS 0x41C80001u
#define NEG1F    0xBF800000        // -1.0f bits

// Scratch (__device__ globals; no allocations allowed)
__device__ unsigned g_mask[GBLK * CPBLK];   // 2 MB chunk validity bitmasks
__device__ int      g_soff[GBLK * CPBLK];   // 2 MB intra-block chunk offsets
__device__ int      g_bcnt[GBLK];
__device__ int      g_boff[GBLK];

// ---------------------------------------------------------------------------
// K1: count — triangular ballots into smem, shfl block scan, dump to global.
// No inter-block communication (no spin).
// ---------------------------------------------------------------------------
__global__ void __launch_bounds__(THREADS) count_kernel(const float* __restrict__ x) {
    __shared__ float sx[NN];
    __shared__ float sy[NN];
    __shared__ float sz[NN];
    __shared__ unsigned smask[CPBLK];
    __shared__ int wtot[8];
    __shared__ int wexc[8];

    const int g  = blockIdx.x;
    const int b  = g >> 8;
    const int r0 = (g & 255) * RPB;
    const int t  = threadIdx.x;
    const int w  = t >> 5;
    const int lane = t & 31;
    const float* xb = x + (size_t)b * NN * 3;

    for (int idx = t; idx < NN * 3; idx += THREADS) {
        float v = xb[idx];
        int pt = idx / 3, c3 = idx - pt * 3;
        if (c3 == 0) sx[pt] = v; else if (c3 == 1) sy[pt] = v; else sz[pt] = v;
    }
    smask[2 * t]     = 0;
    smask[2 * t + 1] = 0;
    __syncthreads();

    const float thr = __uint_as_float(THR_BITS);
    #pragma unroll
    for (int r = 0; r < RPB; r++) {
        const int i = r0 + r;
        const float xi = sx[i], yi = sy[i], zi = sz[i];
        const int nch = (NN - 1 - i + 31) >> 5;     // active chunks this row
        for (int c = w; c < nch; c += 8) {
            int j = i + 1 + (c << 5) + lane;
            int valid = 0;
            if (j < NN) {
                float dx = __fsub_rn(xi, sx[j]);
                float dy = __fsub_rn(yi, sy[j]);
                float dz = __fsub_rn(zi, sz[j]);
                float d2 = __fadd_rn(__fadd_rn(__fmul_rn(dx, dx), __fmul_rn(dy, dy)),
                                     __fmul_rn(dz, dz));
                valid = (d2 <= thr);
            }
            unsigned m = __ballot_sync(FULL, valid);
            if (lane == 0) smask[r * MAXC + c] = m;
        }
    }
    __syncthreads();

    // block scan over 512 chunk popcounts (2 per thread, shfl-based)
    unsigned m0 = smask[2 * t], m1 = smask[2 * t + 1];
    int p0 = __popc(m0);
    int p  = p0 + __popc(m1);
    int inc = p;
    #pragma unroll
    for (int d = 1; d < 32; d <<= 1) {
        int v = __shfl_up_sync(FULL, inc, d);
        if (lane >= d) inc += v;
    }
    if (lane == 31) wtot[w] = inc;
    __syncthreads();
    if (t < 32) {
        int vw = (lane < 8) ? wtot[lane] : 0;
        int winc = vw;
        #pragma unroll
        for (int d = 1; d < 8; d <<= 1) {
            int v = __shfl_up_sync(FULL, winc, d);
            if (lane >= d) winc += v;
        }
        if (lane < 8) wexc[lane] = winc - vw;
        if (lane == 7) g_bcnt[g] = winc;
    }
    __syncthreads();
    const int e0 = wexc[w] + (inc - p);

    // coalesced dump: masks + intra-block offsets
    g_mask[g * CPBLK + 2 * t]     = m0;
    g_mask[g * CPBLK + 2 * t + 1] = m1;
    g_soff[g * CPBLK + 2 * t]     = e0;
    g_soff[g * CPBLK + 2 * t + 1] = e0 + p0;
}

// ---------------------------------------------------------------------------
// K2: exclusive scan of 1024 block counts — one block, shfl-based
// ---------------------------------------------------------------------------
__global__ void __launch_bounds__(1024) scan_kernel() {
    __shared__ int wsum[32];
    const int t = threadIdx.x;
    const int w = t >> 5;
    const int lane = t & 31;

    int c = g_bcnt[t];
    int inc = c;
    #pragma unroll
    for (int d = 1; d < 32; d <<= 1) {
        int v = __shfl_up_sync(FULL, inc, d);
        if (lane >= d) inc += v;
    }
    if (lane == 31) wsum[w] = inc;
    __syncthreads();
    if (t < 32) {
        int vw = wsum[lane];
        int winc = vw;
        #pragma unroll
        for (int d = 1; d < 32; d <<= 1) {
            int v = __shfl_up_sync(FULL, winc, d);
            if (lane >= d) winc += v;
        }
        wsum[lane] = winc - vw;
    }
    __syncthreads();
    g_boff[t] = wsum[w] + inc - c;
}

// ---------------------------------------------------------------------------
// K3: fill whole output with -1.0f — grid-stride, 8 int4 per thread
// ---------------------------------------------------------------------------
#define FILLB 2048
__global__ void __launch_bounds__(256) fill_kernel(int4* __restrict__ out) {
    const int NV = 2 * TOTALF / 4;   // 4,192,256 int4 vectors
    int4 mm; mm.x = mm.y = mm.z = mm.w = NEG1F;
    int v = blockIdx.x * 256 + threadIdx.x;
    #pragma unroll
    for (int it = 0; it < 8; it++) {
        if (v < NV) out[v] = mm;
        v += FILLB * 256;
    }
}

// ---------------------------------------------------------------------------
// K4: scatter — read (mask, off) + block base, write edges (overwrites fill)
// ---------------------------------------------------------------------------
__global__ void __launch_bounds__(THREADS) scatter_kernel(float* __restrict__ out0,
                                                          float* __restrict__ out1) {
    const int g  = blockIdx.x;
    const int b  = g >> 8;
    const int r0 = (g & 255) * RPB;
    const int t  = threadIdx.x;
    const int w  = t >> 5;
    const int lane = t & 31;
    const unsigned lt = (1u << lane) - 1u;
    const int base = g_boff[g];
    const int bofs = b * NN;
    const unsigned* mblk = &g_mask[g * CPBLK];
    const int* oblk = &g_soff[g * CPBLK];

    #pragma unroll
    for (int r = 0; r < RPB; r++) {
        const int i = r0 + r;
        const int nch = (NN - 1 - i + 31) >> 5;
        for (int c = w; c < nch; c += 8) {
            unsigned m = mblk[r * MAXC + c];
            if (m & (1u << lane)) {
                int j = i + 1 + (c << 5) + lane;
                int pos = base + oblk[r * MAXC + c] + __popc(m & lt);
                out0[pos] = (float)(bofs + i);
                out1[pos] = (float)(bofs + j);
            }
        }
    }
}

extern "C" void kernel_launch(void* const* d_in, const int* in_sizes, int n_in,
                              void* d_out, int out_size) {
    const float* x = (const float*)d_in[0];
    float* out = (float*)d_out;
    (void)in_sizes; (void)n_in; (void)out_size;

    count_kernel<<<GBLK, THREADS>>>(x);
    scan_kernel<<<1, 1024>>>();
    fill_kernel<<<FILLB, 256>>>((int4*)out);
    scatter_kernel<<<GBLK, THREADS>>>(out, out + TOTALF);
}

// round 12
// speedup vs baseline: 1.4071x; 1.4071x over previous
#include <cuda_runtime.h>
#include <cstdint>

// Problem constants
#define NB      4
#define NN      2048
#define PP      2096128            // NN*(NN-1)/2
#define TOTALF  (NB*PP)            // 8384512 flat pair slots per output row
#define RPB     8                  // rows per block
#define GBLK    (NB * (NN / RPB))  // 1024 blocks
#define MAXC    64                 // max j-chunks (32 pairs) per row
#define CPBLK   (RPB * MAXC)       // 512 mask slots per block
#define THREADS 256
#define FULL    0xffffffffu

// d2 <= 25.0f + 1ulp  <=>  sqrtf(d2) <= 5.0f (correctly rounded sqrt)
#define THR_BITS 0x41C80001u
#define NEG1F    0xBF800000        // -1.0f bits

#define FILLB   2048               // fill blocks inside combo kernel

// Scratch (__device__ globals; no allocations allowed)
__device__ unsigned g_mask[GBLK * CPBLK];   // 2 MB chunk validity bitmasks
__device__ int      g_soff[GBLK * CPBLK];   // 2 MB intra-block chunk offsets
__device__ int      g_bcnt[GBLK];
__device__ int      g_boff[GBLK];
__device__ int      g_total;

// ---------------------------------------------------------------------------
// K1: count — triangular ballots into smem, shfl block scan, coalesced dump.
// ---------------------------------------------------------------------------
__global__ void __launch_bounds__(THREADS) count_kernel(const float* __restrict__ x) {
    __shared__ float sx[NN];
    __shared__ float sy[NN];
    __shared__ float sz[NN];
    __shared__ unsigned smask[CPBLK];
    __shared__ int wtot[8];
    __shared__ int wexc[8];

    const int g  = blockIdx.x;
    const int b  = g >> 8;
    const int r0 = (g & 255) * RPB;
    const int t  = threadIdx.x;
    const int w  = t >> 5;
    const int lane = t & 31;
    const float* xb = x + (size_t)b * NN * 3;

    for (int idx = t; idx < NN * 3; idx += THREADS) {
        float v = xb[idx];
        int pt = idx / 3, c3 = idx - pt * 3;
        if (c3 == 0) sx[pt] = v; else if (c3 == 1) sy[pt] = v; else sz[pt] = v;
    }
    smask[2 * t]     = 0;
    smask[2 * t + 1] = 0;
    __syncthreads();

    const float thr = __uint_as_float(THR_BITS);
    #pragma unroll
    for (int r = 0; r < RPB; r++) {
        const int i = r0 + r;
        const float xi = sx[i], yi = sy[i], zi = sz[i];
        const int nch = (NN - 1 - i + 31) >> 5;     // active chunks this row
        for (int c = w; c < nch; c += 8) {
            int j = i + 1 + (c << 5) + lane;
            int valid = 0;
            if (j < NN) {
                float dx = __fsub_rn(xi, sx[j]);
                float dy = __fsub_rn(yi, sy[j]);
                float dz = __fsub_rn(zi, sz[j]);
                float d2 = __fadd_rn(__fadd_rn(__fmul_rn(dx, dx), __fmul_rn(dy, dy)),
                                     __fmul_rn(dz, dz));
                valid = (d2 <= thr);
            }
            unsigned m = __ballot_sync(FULL, valid);
            if (lane == 0) smask[r * MAXC + c] = m;
        }
    }
    __syncthreads();

    // block scan over 512 chunk popcounts (2 per thread, shfl-based)
    unsigned m0 = smask[2 * t], m1 = smask[2 * t + 1];
    int p0 = __popc(m0);
    int p  = p0 + __popc(m1);
    int inc = p;
    #pragma unroll
    for (int d = 1; d < 32; d <<= 1) {
        int v = __shfl_up_sync(FULL, inc, d);
        if (lane >= d) inc += v;
    }
    if (lane == 31) wtot[w] = inc;
    __syncthreads();
    if (t < 32) {
        int vw = (lane < 8) ? wtot[lane] : 0;
        int winc = vw;
        #pragma unroll
        for (int d = 1; d < 8; d <<= 1) {
            int v = __shfl_up_sync(FULL, winc, d);
            if (lane >= d) winc += v;
        }
        if (lane < 8) wexc[lane] = winc - vw;
        if (lane == 7) g_bcnt[g] = winc;
    }
    __syncthreads();
    const int e0 = wexc[w] + (inc - p);

    g_mask[g * CPBLK + 2 * t]     = m0;
    g_mask[g * CPBLK + 2 * t + 1] = m1;
    g_soff[g * CPBLK + 2 * t]     = e0;
    g_soff[g * CPBLK + 2 * t + 1] = e0 + p0;
}

// ---------------------------------------------------------------------------
// K2: exclusive scan of 1024 block counts — one block, shfl-based
// ---------------------------------------------------------------------------
__global__ void __launch_bounds__(1024) scan_kernel() {
    __shared__ int wsum[32];
    const int t = threadIdx.x;
    const int w = t >> 5;
    const int lane = t & 31;

    int c = g_bcnt[t];
    int inc = c;
    #pragma unroll
    for (int d = 1; d < 32; d <<= 1) {
        int v = __shfl_up_sync(FULL, inc, d);
        if (lane >= d) inc += v;
    }
    if (lane == 31) wsum[w] = inc;
    __syncthreads();
    if (t < 32) {
        int vw = wsum[lane];
        int winc = vw;
        #pragma unroll
        for (int d = 1; d < 32; d <<= 1) {
            int v = __shfl_up_sync(FULL, winc, d);
            if (lane >= d) winc += v;
        }
        wsum[lane] = winc - vw;
    }
    __syncthreads();
    g_boff[t] = wsum[w] + inc - c;
    if (t == 1023) g_total = wsum[w] + inc;
}

// ---------------------------------------------------------------------------
// K3: combo — fill blocks write -1.0f over the invalid tail [total, TOTALF)
// of both rows; scatter blocks write valid edges in [0, total). Disjoint.
// ---------------------------------------------------------------------------
__global__ void __launch_bounds__(256) combo_kernel(float* __restrict__ out) {
    const int t = threadIdx.x;

    if (blockIdx.x < FILLB) {
        // ---- fill role: grid-stride over int4 vectors, tail only
        const int total = g_total;
        const int NV = 2 * TOTALF / 4;       // TOTALF % 4 == 0: no row straddle
        int4 mm; mm.x = mm.y = mm.z = mm.w = NEG1F;
        int v = blockIdx.x * 256 + t;
        #pragma unroll
        for (int it = 0; it < 8; it++) {
            if (v < NV) {
                const int q0 = v * 4;
                const int local = (q0 < TOTALF) ? q0 : q0 - TOTALF;
                if (local >= total) {
                    reinterpret_cast<int4*>(out)[v] = mm;
                } else if (local + 4 > total) {
                    #pragma unroll
                    for (int e = 0; e < 4; e++)
                        if (local + e >= total) out[q0 + e] = -1.0f;
                }
            }
            v += FILLB * 256;
        }
        return;
    }

    // ---- scatter role: one coalesced wide load per thread, bit-iterate locally
    const int g  = blockIdx.x - FILLB;
    const int b  = g >> 8;
    const int r0 = (g & 255) * RPB;
    const int base = g_boff[g];
    const int bofs = b * NN;
    float* out0 = out;
    float* out1 = out + TOTALF;

    const uint2 mm2 = *reinterpret_cast<const uint2*>(&g_mask[g * CPBLK + 2 * t]);
    const int2  oo2 = *reinterpret_cast<const int2*>(&g_soff[g * CPBLK + 2 * t]);

    #pragma unroll
    for (int s = 0; s < 2; s++) {
        unsigned m = s ? mm2.y : mm2.x;
        if (!m) continue;
        int off = base + (s ? oo2.y : oo2.x);
        const int ch = 2 * t + s;
        const int r = ch >> 6;           // chunk -> row within block
        const int c = ch & 63;           // chunk -> j-chunk
        const int i = r0 + r;
        const float fi = (float)(bofs + i);
        const int jb = bofs + i + 1 + (c << 5);
        while (m) {
            int bit = __ffs(m) - 1;
            m &= m - 1;
            out0[off] = fi;
            out1[off] = (float)(jb + bit);
            off++;
        }
    }
}

extern "C" void kernel_launch(void* const* d_in, const int* in_sizes, int n_in,
                              void* d_out, int out_size) {
    const float* x = (const float*)d_in[0];
    float* out = (float*)d_out;
    (void)in_sizes; (void)n_in; (void)out_size;

    count_kernel<<<GBLK, THREADS>>>(x);
    scan_kernel<<<1, 1024>>>();
    combo_kernel<<<FILLB + GBLK, 256>>>(out);
}

// round 13
// speedup vs baseline: 1.7055x; 1.2121x over previous
#include <cuda_runtime.h>
#include <cstdint>

// Problem constants
#define NB      4
#define NN      2048
#define PP      2096128            // NN*(NN-1)/2
#define TOTALF  (NB*PP)            // 8384512 flat pair slots per output row
#define RPB     16                 // rows per block
#define GPB     (NN / RPB)         // 128 row-groups per batch
#define GBLK    (NB * GPB)         // 512 blocks
#define MAXC    64                 // max j-chunks (32 pairs) per row
#define CPBLK   (RPB * MAXC)       // 1024 mask slots per block
#define THREADS 256
#define FULL    0xffffffffu
#define NPAD    2080               // points + sentinel pad (covers j <= 2078)

// d2 <= 25.0f + 1ulp  <=>  sqrtf(d2) <= 5.0f (correctly rounded sqrt)
#define THR_BITS 0x41C80001u
#define NEG1F    0xBF800000        // -1.0f bits

#define FILLB   2048               // fill blocks inside combo kernel

// Scratch (__device__ globals; no allocations allowed)
__device__ unsigned g_mask[GBLK * CPBLK];   // 2 MB chunk validity bitmasks
__device__ int      g_soff[GBLK * CPBLK];   // 2 MB intra-block chunk offsets
__device__ int      g_bcnt[GBLK];
__device__ int      g_boff[GBLK];
__device__ int      g_total;

// ---------------------------------------------------------------------------
// K1: count — float4-staged interleaved xyz smem, sentinel-padded (no bounds
// check), triangular ballots, shfl block scan, wide coalesced dump.
// ---------------------------------------------------------------------------
__global__ void __launch_bounds__(THREADS) count_kernel(const float* __restrict__ x) {
    __shared__ float sp[NPAD * 3];          // interleaved x,y,z per point
    __shared__ unsigned smask[CPBLK];
    __shared__ int wtot[8];
    __shared__ int wexc[8];

    const int g  = blockIdx.x;
    const int b  = g >> 7;                  // batch
    const int r0 = (g & 127) * RPB;         // first row of this block
    const int t  = threadIdx.x;
    const int w  = t >> 5;
    const int lane = t & 31;

    // stage: 1536 float4 = 6144 floats, straight copy (no div/mod)
    const float4* xb4 = reinterpret_cast<const float4*>(x + (size_t)b * NN * 3);
    float4* sp4 = reinterpret_cast<float4*>(sp);
    #pragma unroll
    for (int it = 0; it < 6; it++) sp4[it * 256 + t] = xb4[it * 256 + t];
    if (t < (NPAD - NN) * 3) sp[NN * 3 + t] = 1e30f;   // sentinel pad
    #pragma unroll
    for (int s = 0; s < 4; s++) smask[4 * t + s] = 0;
    __syncthreads();

    const float thr = __uint_as_float(THR_BITS);
    #pragma unroll 4
    for (int r = 0; r < RPB; r++) {
        const int i = r0 + r;
        const float xi = sp[3 * i], yi = sp[3 * i + 1], zi = sp[3 * i + 2];
        const int nch = (NN - 1 - i + 31) >> 5;         // active chunks this row
        for (int c = w; c < nch; c += 8) {
            const float* pj = &sp[3 * (i + 1 + (c << 5) + lane)];
            float dx = __fsub_rn(xi, pj[0]);
            float dy = __fsub_rn(yi, pj[1]);
            float dz = __fsub_rn(zi, pj[2]);
            float d2 = __fadd_rn(__fadd_rn(__fmul_rn(dx, dx), __fmul_rn(dy, dy)),
                                 __fmul_rn(dz, dz));
            unsigned m = __ballot_sync(FULL, d2 <= thr);
            if (lane == 0) smask[(r << 6) + c] = m;
        }
    }
    __syncthreads();

    // block scan over 1024 chunk popcounts (4 per thread, shfl-based)
    const uint4 mv = reinterpret_cast<const uint4*>(smask)[t];
    const int pc0 = __popc(mv.x), pc1 = __popc(mv.y);
    const int pc2 = __popc(mv.z), pc3 = __popc(mv.w);
    const int p = pc0 + pc1 + pc2 + pc3;
    int inc = p;
    #pragma unroll
    for (int d = 1; d < 32; d <<= 1) {
        int v = __shfl_up_sync(FULL, inc, d);
        if (lane >= d) inc += v;
    }
    if (lane == 31) wtot[w] = inc;
    __syncthreads();
    if (t < 32) {
        int vw = (lane < 8) ? wtot[lane] : 0;
        int winc = vw;
        #pragma unroll
        for (int d = 1; d < 8; d <<= 1) {
            int v = __shfl_up_sync(FULL, winc, d);
            if (lane >= d) winc += v;
        }
        if (lane < 8) wexc[lane] = winc - vw;
        if (lane == 7) g_bcnt[g] = winc;
    }
    __syncthreads();
    const int e0 = wexc[w] + (inc - p);

    reinterpret_cast<uint4*>(&g_mask[g * CPBLK])[t] = mv;
    int4 ov;
    ov.x = e0; ov.y = e0 + pc0; ov.z = e0 + pc0 + pc1; ov.w = e0 + pc0 + pc1 + pc2;
    reinterpret_cast<int4*>(&g_soff[g * CPBLK])[t] = ov;
}

// ---------------------------------------------------------------------------
// K2: exclusive scan of 512 block counts — one block, shfl-based
// ---------------------------------------------------------------------------
__global__ void __launch_bounds__(512) scan_kernel() {
    __shared__ int wsum[16];
    const int t = threadIdx.x;
    const int w = t >> 5;
    const int lane = t & 31;

    int c = g_bcnt[t];
    int inc = c;
    #pragma unroll
    for (int d = 1; d < 32; d <<= 1) {
        int v = __shfl_up_sync(FULL, inc, d);
        if (lane >= d) inc += v;
    }
    if (lane == 31) wsum[w] = inc;
    __syncthreads();
    if (t < 32) {
        int vw = (lane < 16) ? wsum[lane] : 0;
        int winc = vw;
        #pragma unroll
        for (int d = 1; d < 16; d <<= 1) {
            int v = __shfl_up_sync(FULL, winc, d);
            if (lane >= d) winc += v;
        }
        if (lane < 16) wsum[lane] = winc - vw;
    }
    __syncthreads();
    g_boff[t] = wsum[w] + inc - c;
    if (t == 511) g_total = wsum[w] + inc;
}

// ---------------------------------------------------------------------------
// K3: combo — fill blocks write -1.0f over the invalid tail [total, TOTALF)
// of both rows; scatter blocks write valid edges in [0, total). Disjoint.
// ---------------------------------------------------------------------------
__global__ void __launch_bounds__(256) combo_kernel(float* __restrict__ out) {
    const int t = threadIdx.x;

    if (blockIdx.x < FILLB) {
        // ---- fill role: grid-stride over int4 vectors, tail only
        const int total = g_total;
        const int NV = 2 * TOTALF / 4;       // TOTALF % 4 == 0: no row straddle
        int4 mm; mm.x = mm.y = mm.z = mm.w = NEG1F;
        int v = blockIdx.x * 256 + t;
        #pragma unroll
        for (int it = 0; it < 8; it++) {
            if (v < NV) {
                const int q0 = v * 4;
                const int local = (q0 < TOTALF) ? q0 : q0 - TOTALF;
                if (local >= total) {
                    reinterpret_cast<int4*>(out)[v] = mm;
                } else if (local + 4 > total) {
                    #pragma unroll
                    for (int e = 0; e < 4; e++)
                        if (local + e >= total) out[q0 + e] = -1.0f;
                }
            }
            v += FILLB * 256;
        }
        return;
    }

    // ---- scatter role: wide coalesced loads, bit-iterate locally
    const int g  = blockIdx.x - FILLB;
    const int b  = g >> 7;
    const int r0 = (g & 127) * RPB;
    const int base = g_boff[g];
    const int bofs = b * NN;
    float* out0 = out;
    float* out1 = out + TOTALF;

    const uint4 mv = reinterpret_cast<const uint4*>(&g_mask[g * CPBLK])[t];
    const int4  ov = reinterpret_cast<const int4*>(&g_soff[g * CPBLK])[t];
    const unsigned ma[4] = {mv.x, mv.y, mv.z, mv.w};
    const int      oa[4] = {ov.x, ov.y, ov.z, ov.w};

    #pragma unroll
    for (int s = 0; s < 4; s++) {
        unsigned m = ma[s];
        if (!m) continue;
        int off = base + oa[s];
        const int ch = 4 * t + s;
        const int r = ch >> 6;               // row within block
        const int c = ch & 63;               // j-chunk
        const int i = r0 + r;
        const float fi = (float)(bofs + i);
        const int jb = bofs + i + 1 + (c << 5);
        while (m) {
            int bit = __ffs(m) - 1;
            m &= m - 1;
            out0[off] = fi;
            out1[off] = (float)(jb + bit);
            off++;
        }
    }
}

extern "C" void kernel_launch(void* const* d_in, const int* in_sizes, int n_in,
                              void* d_out, int out_size) {
    const float* x = (const float*)d_in[0];
    float* out = (float*)d_out;
    (void)in_sizes; (void)n_in; (void)out_size;

    count_kernel<<<GBLK, THREADS>>>(x);
    scan_kernel<<<1, 512>>>();
    combo_kernel<<<FILLB + GBLK, 256>>>(out);
}

// round 15
// speedup vs baseline: 1.8173x; 1.0656x over previous
#include <cuda_runtime.h>
#include <cstdint>

// Problem constants
#define NB      4
#define NN      2048
#define PP      2096128            // NN*(NN-1)/2
#define TOTALF  (NB*PP)            // 8384512 flat pair slots per output row
#define RPG     8                  // rows per group (ordering/compaction unit)
#define SPB     256                // groups per batch
#define NGRP    (NB * SPB)         // 1024 groups
#define CPGRP   (RPG * 64)         // 512 chunk slots per group
#define CBLK    512                // count blocks (each = 2 folded groups)
#define THREADS 256
#define FULL    0xffffffffu
#define NPAD    2080               // points + sentinel pad (covers j <= 2078)

// d2 <= 25.0f + 1ulp  <=>  sqrtf(d2) <= 5.0f (correctly rounded sqrt)
#define THR_BITS 0x41C80001u
#define NEG1F    0xBF800000        // -1.0f bits

#define FILLB   2048               // fill blocks inside combo kernel

// Scratch (__device__ globals; no allocations allowed)
__device__ unsigned g_mask[NGRP * CPGRP];   // 2 MB chunk validity bitmasks (per group)
__device__ int      g_soff[NGRP * CPGRP];   // 2 MB intra-group chunk offsets
__device__ int      g_gcnt[NGRP];
__device__ int      g_goff[NGRP];
__device__ int      g_total;

// ---------------------------------------------------------------------------
// K1: count — folded group pair (s, 255-s) per block for balance; sentinel-
// padded interleaved smem; triangular ballots; one 1024-chunk block scan.
// ---------------------------------------------------------------------------
__global__ void __launch_bounds__(THREADS) count_kernel(const float* __restrict__ x) {
    __shared__ float sp[NPAD * 3];          // interleaved x,y,z per point
    __shared__ unsigned smask[2 * CPGRP];   // [0,512)=lo group, [512,1024)=hi
    __shared__ int wtot[8];
    __shared__ int wexc[8];
    __shared__ int s_cntlo;
    __shared__ int s_tot;

    const int k  = blockIdx.x;
    const int b  = k >> 7;                  // batch
    const int f  = k & 127;                 // fold index
    const int s_lo = f;
    const int s_hi = 255 - f;
    const int t  = threadIdx.x;
    const int w  = t >> 5;
    const int lane = t & 31;

    // stage: 1536 float4 = 6144 floats, straight copy (no div/mod)
    const float4* xb4 = reinterpret_cast<const float4*>(x + (size_t)b * NN * 3);
    float4* sp4 = reinterpret_cast<float4*>(sp);
    #pragma unroll
    for (int it = 0; it < 6; it++) sp4[it * 256 + t] = xb4[it * 256 + t];
    if (t < (NPAD - NN) * 3) sp[NN * 3 + t] = 1e30f;   // sentinel pad
    #pragma unroll
    for (int s4 = 0; s4 < 4; s4++) smask[4 * t + s4] = 0;
    __syncthreads();

    const float thr = __uint_as_float(THR_BITS);
    #pragma unroll
    for (int h = 0; h < 2; h++) {
        const int r0 = (h ? s_hi : s_lo) * RPG;
        #pragma unroll
        for (int r = 0; r < RPG; r++) {
            const int i = r0 + r;
            const float xi = sp[3 * i], yi = sp[3 * i + 1], zi = sp[3 * i + 2];
            const int nch = (NN - 1 - i + 31) >> 5;     // active chunks this row
            for (int c = w; c < nch; c += 8) {
                const float* pj = &sp[3 * (i + 1 + (c << 5) + lane)];
                float dx = __fsub_rn(xi, pj[0]);
                float dy = __fsub_rn(yi, pj[1]);
                float dz = __fsub_rn(zi, pj[2]);
                float d2 = __fadd_rn(__fadd_rn(__fmul_rn(dx, dx), __fmul_rn(dy, dy)),
                                     __fmul_rn(dz, dz));
                unsigned m = __ballot_sync(FULL, d2 <= thr);
                if (lane == 0) smask[(h << 9) + (r << 6) + c] = m;
            }
        }
    }
    __syncthreads();

    // block scan over 1024 chunk popcounts (4 per thread, shfl-based)
    const uint4 mv = reinterpret_cast<const uint4*>(smask)[t];
    const int pc0 = __popc(mv.x), pc1 = __popc(mv.y);
    const int pc2 = __popc(mv.z), pc3 = __popc(mv.w);
    const int p = pc0 + pc1 + pc2 + pc3;
    int inc = p;
    #pragma unroll
    for (int d = 1; d < 32; d <<= 1) {
        int v = __shfl_up_sync(FULL, inc, d);
        if (lane >= d) inc += v;
    }
    if (lane == 31) wtot[w] = inc;
    __syncthreads();
    if (t < 32) {
        int vw = (lane < 8) ? wtot[lane] : 0;
        int winc = vw;
        #pragma unroll
        for (int d = 1; d < 8; d <<= 1) {
            int v = __shfl_up_sync(FULL, winc, d);
            if (lane >= d) winc += v;
        }
        if (lane < 8) wexc[lane] = winc - vw;
        if (lane == 7) s_tot = winc;
    }
    __syncthreads();
    const int e0 = wexc[w] + (inc - p);
    if (t == 128) s_cntlo = e0;     // exclusive prefix at chunk 512 = lo-group count
    __syncthreads();

    const int cnt_lo = s_cntlo;
    const int gi_lo = b * SPB + s_lo;
    const int gi_hi = b * SPB + s_hi;
    if (t == 0) {
        g_gcnt[gi_lo] = cnt_lo;
        g_gcnt[gi_hi] = s_tot - cnt_lo;
    }

    // dump per-group masks + intra-group offsets (hi rebased by cnt_lo)
    const int gi   = (t < 128) ? gi_lo : gi_hi;
    const int rb   = (t < 128) ? 0 : cnt_lo;
    const int slot = (4 * t) & 511;         // chunk index within group
    reinterpret_cast<uint4*>(&g_mask[gi * CPGRP + slot])[0] = mv;
    int4 ov;
    ov.x = e0 - rb; ov.y = ov.x + pc0; ov.z = ov.y + pc1; ov.w = ov.z + pc2;
    reinterpret_cast<int4*>(&g_soff[gi * CPGRP + slot])[0] = ov;
}

// ---------------------------------------------------------------------------
// K2: exclusive scan of 1024 group counts — one block, shfl-based
// ---------------------------------------------------------------------------
__global__ void __launch_bounds__(1024) scan_kernel() {
    __shared__ int wsum[32];
    const int t = threadIdx.x;
    const int w = t >> 5;
    const int lane = t & 31;

    int c = g_gcnt[t];
    int inc = c;
    #pragma unroll
    for (int d = 1; d < 32; d <<= 1) {
        int v = __shfl_up_sync(FULL, inc, d);
        if (lane >= d) inc += v;
    }
    if (lane == 31) wsum[w] = inc;
    __syncthreads();
    if (t < 32) {
        int vw = wsum[lane];
        int winc = vw;
        #pragma unroll
        for (int d = 1; d < 32; d <<= 1) {
            int v = __shfl_up_sync(FULL, winc, d);
            if (lane >= d) winc += v;
        }
        wsum[lane] = winc - vw;
    }
    __syncthreads();
    g_goff[t] = wsum[w] + inc - c;
    if (t == 1023) g_total = wsum[w] + inc;
}

// ---------------------------------------------------------------------------
// K3: combo — fill blocks write -1.0f over the invalid tail [total, TOTALF)
// of both rows; scatter blocks (one per group) write edges in [0, total).
// ---------------------------------------------------------------------------
__global__ void __launch_bounds__(256) combo_kernel(float* __restrict__ out) {
    const int t = threadIdx.x;

    if (blockIdx.x < FILLB) {
        // ---- fill role: grid-stride over int4 vectors, tail only
        const int total = g_total;
        const int NV = 2 * TOTALF / 4;       // TOTALF % 4 == 0: no row straddle
        int4 mm; mm.x = mm.y = mm.z = mm.w = NEG1F;
        int v = blockIdx.x * 256 + t;
        #pragma unroll
        for (int it = 0; it < 8; it++) {
            if (v < NV) {
                const int q0 = v * 4;
                const int local = (q0 < TOTALF) ? q0 : q0 - TOTALF;
                if (local >= total) {
                    reinterpret_cast<int4*>(out)[v] = mm;
                } else if (local + 4 > total) {
                    #pragma unroll
                    for (int e = 0; e < 4; e++)
                        if (local + e >= total) out[q0 + e] = -1.0f;
                }
            }
            v += FILLB * 256;
        }
        return;
    }

    // ---- scatter role: one block per group; uint2 wide loads, local bit-iter
    const int gi = blockIdx.x - FILLB;
    const int b  = gi >> 8;
    const int r0 = (gi & 255) * RPG;
    const int base = g_goff[gi];
    const int bofs = b * NN;
    float* out0 = out;
    float* out1 = out + TOTALF;

    const uint2 mm2 = *reinterpret_cast<const uint2*>(&g_mask[gi * CPGRP + 2 * t]);
    const int2  oo2 = *reinterpret_cast<const int2*>(&g_soff[gi * CPGRP + 2 * t]);

    #pragma unroll
    for (int s = 0; s < 2; s++) {
        unsigned m = s ? mm2.y : mm2.x;
        if (!m) continue;
        int off = base + (s ? oo2.y : oo2.x);
        const int ch = 2 * t + s;
        const int r = ch >> 6;               // row within group
        const int c = ch & 63;               // j-chunk
        const int i = r0 + r;
        const float fi = (float)(bofs + i);
        const int jb = bofs + i + 1 + (c << 5);
        while (m) {
            int bit = __ffs(m) - 1;
            m &= m - 1;
            out0[off] = fi;
            out1[off] = (float)(jb + bit);
            off++;
        }
    }
}

extern "C" void kernel_launch(void* const* d_in, const int* in_sizes, int n_in,
                              void* d_out, int out_size) {
    const float* x = (const float*)d_in[0];
    float* out = (float*)d_out;
    (void)in_sizes; (void)n_in; (void)out_size;

    count_kernel<<<CBLK, THREADS>>>(x);
    scan_kernel<<<1, 1024>>>();
    combo_kernel<<<FILLB + NGRP, 256>>>(out);
}